// round 14
// baseline (speedup 1.0000x reference)
#include <cuda_runtime.h>
#include <cuda_bf16.h>
#include <cstdint>

#define B_ 32
#define D_ 128
#define T_ 2250
#define Q_ 32
#define K_ 1024
#define N_ (B_*T_)          // 72000
#define NBLK 563            // ceil(N/128)
#define WIN 0.02f
#define NC 3                // candidate slots per lane per point

#define EPITCH 392          // bf16 per padded row (784 B)
#define ROWB 784
#define KSP 12              // k16-steps per warp (K split 2-way)

__device__ __align__(16) float g_resid[(size_t)N_ * D_];
__device__ __align__(16) float g_cnorm[Q_ * K_];
__device__ __align__(16) __nv_bfloat16 g_e2[(size_t)Q_ * K_ * EPITCH];

// ---------------------------------------------------------------------------
__global__ void transpose_kernel(const float* __restrict__ in)
{
    __shared__ float tile[32][33];
    const int b  = blockIdx.z;
    const int t0 = blockIdx.x * 32;
    const int d0 = blockIdx.y * 32;
    const int tx = threadIdx.x;
    const int ty = threadIdx.y;

    #pragma unroll
    for (int k = 0; k < 4; k++) {
        int d = d0 + ty + k * 8;
        int t = t0 + tx;
        float v = 0.0f;
        if (t < T_) v = in[((size_t)b * D_ + d) * T_ + t];
        tile[ty + k * 8][tx] = v;
    }
    __syncthreads();
    #pragma unroll
    for (int k = 0; k < 4; k++) {
        int t = t0 + ty + k * 8;
        int d = d0 + tx;
        if (t < T_) g_resid[((size_t)b * T_ + t) * D_ + d] = tile[tx][ty + k * 8];
    }
}

// ---------------------------------------------------------------------------
__global__ void cnorm_kernel(const float* __restrict__ embed)
{
    const int wid  = threadIdx.x >> 5;
    const int lane = threadIdx.x & 31;
    const int code = blockIdx.x * 8 + wid;
    float s = 0.0f;
    #pragma unroll
    for (int j = 0; j < 4; j++) {
        float v = embed[(size_t)code * D_ + lane + 32 * j];
        s = fmaf(v, v, s);
    }
    #pragma unroll
    for (int d = 16; d; d >>= 1) s += __shfl_xor_sync(0xffffffffu, s, d);
    if (lane == 0) g_cnorm[code] = s;
}

// ---------------------------------------------------------------------------
__global__ void prep_e2_kernel(const float* __restrict__ embed)
{
    const int row = blockIdx.x;
    const int d   = threadIdx.x;
    float v = embed[(size_t)row * D_ + d];
    __nv_bfloat16 hi = __float2bfloat16(v);
    __nv_bfloat16 lo = __float2bfloat16(v - __bfloat162float(hi));
    g_e2[(size_t)row * EPITCH + d]       = hi;
    g_e2[(size_t)row * EPITCH + 128 + d] = lo;
    g_e2[(size_t)row * EPITCH + 256 + d] = hi;
    if (d < 8) g_e2[(size_t)row * EPITCH + 384 + d] = __float2bfloat16(0.0f);
}

// ---------------------------------------------------------------------------
__device__ __forceinline__ uint32_t smem_u32(const void* p) {
    uint32_t a;
    asm("{ .reg .u64 t; cvta.to.shared.u64 t, %1; cvt.u32.u64 %0, t; }"
        : "=r"(a) : "l"(p));
    return a;
}
__device__ __forceinline__ void ldsm_x4(uint32_t& r0, uint32_t& r1,
                                        uint32_t& r2, uint32_t& r3, uint32_t addr)
{
    asm volatile("ldmatrix.sync.aligned.m8n8.x4.shared.b16 {%0,%1,%2,%3}, [%4];"
                 : "=r"(r0), "=r"(r1), "=r"(r2), "=r"(r3) : "r"(addr));
}
__device__ __forceinline__ void mma16816(float* c, const uint32_t* a,
                                         uint32_t b0, uint32_t b1)
{
    asm volatile(
        "mma.sync.aligned.m16n8k16.row.col.f32.bf16.bf16.f32 "
        "{%0,%1,%2,%3}, {%4,%5,%6,%7}, {%8,%9}, {%0,%1,%2,%3};"
        : "+f"(c[0]), "+f"(c[1]), "+f"(c[2]), "+f"(c[3])
        : "r"(a[0]), "r"(a[1]), "r"(a[2]), "r"(a[3]), "r"(b0), "r"(b1));
}
__device__ __forceinline__ void cp_async16(void* smem_dst, const void* gmem_src)
{
    unsigned saddr = (unsigned)__cvta_generic_to_shared(smem_dst);
    asm volatile("cp.async.cg.shared.global [%0], [%1], 16;"
                 :: "r"(saddr), "l"(gmem_src) : "memory");
}
__device__ __forceinline__ void cp_async_commit()
{ asm volatile("cp.async.commit_group;" ::: "memory"); }
__device__ __forceinline__ void cp_async_wait_all()
{ asm volatile("cp.async.wait_group 0;" ::: "memory"); }

#define CAND_UPD(s, idx, mb, cs, ci, cn, ovf) do {                            \
    if ((s) > (mb)) (mb) = (s);                                               \
    if ((s) >= (mb) - WIN) {                                                  \
        if ((cn) < NC) { (cs)[(cn)] = (s); (ci)[(cn)] = (idx); (cn)++; }      \
        else {                                                                \
            int _w = 0;                                                       \
            _Pragma("unroll")                                                 \
            for (int _t = 0; _t < NC; _t++)                                   \
                if ((cs)[_t] >= (mb) - WIN) {                                 \
                    (cs)[_w] = (cs)[_t]; (ci)[_w] = (ci)[_t]; _w++; }         \
            if (_w < NC) { (cs)[_w] = (s); (ci)[_w] = (idx); (cn) = _w + 1; } \
            else (ovf) = 1;                                                   \
        }                                                                     \
    }                                                                         \
} while (0)

// ---------------------------------------------------------------------------
// HMMA RVQ layer, K-split across warp pairs for 16-warp occupancy.
// 512 threads = 16 warps; warps w and w+8 share M-rows [(w&7)*16, ...+16):
// w: k-steps 0..11, w+8: 12..23. Upper warps dump partial accs to smem;
// lower warps combine + windowed scan. Exact fp32 rescore (R7 f32x2 order,
// first-max tie-break) selects the final index -> indices bit-identical.
// smem: B dbl-buf 2x50176 (A staging reuse) + partials 32768 + cn + sidx.
// ---------------------------------------------------------------------------
#define SM_BUF0 0
#define SM_BUF1 50176
#define SM_PART 100352       // 8 warps x 32 lanes x 32 floats = 32768 B
#define SM_CN   133120
#define SM_SIDX 137216
#define SM_TOTAL 137728

__global__ void __launch_bounds__(512, 1)
rvq_mma_kernel(const float* __restrict__ embed, int q, float* __restrict__ out)
{
    extern __shared__ char smem[];
    float*  gcn  = (float*)(smem + SM_CN);
    int*    sidx = (int*)(smem + SM_SIDX);
    float4* part = (float4*)(smem + SM_PART);
    const uint32_t sbase = smem_u32(smem);

    const int tid  = threadIdx.x;
    const int wid  = tid >> 5;
    const int lane = tid & 31;
    const int wlo  = wid & 7;            // M-row group
    const int upper = wid >> 3;          // 0 = k 0..11, 1 = k 12..23
    const int blockStart = blockIdx.x * 128;

    // ---- cnorm -> smem ----
    for (int u = tid; u < K_; u += 512) gcn[u] = g_cnorm[q * K_ + u];

    // ---- build A' staging = [r_hi | r_hi | r_lo] (128 x 384 bf16) ----
    for (int u = tid; u < 128 * 48; u += 512) {
        int row = u / 48, g = u % 48;
        int sec = g >> 4;
        int dbase = (g & 15) * 8;
        int n = blockStart + row;
        if (n >= N_) n = 0;
        const float* rr = g_resid + (size_t)n * D_;
        union { __nv_bfloat16 h[8]; uint4 v; } pk;
        #pragma unroll
        for (int j = 0; j < 8; j++) {
            float v = rr[dbase + j];
            __nv_bfloat16 hi = __float2bfloat16(v);
            pk.h[j] = (sec < 2) ? hi : __float2bfloat16(v - __bfloat162float(hi));
        }
        *(uint4*)(smem + row * ROWB + g * 16) = pk.v;
    }
    __syncthreads();

    // ---- A fragments -> registers (this warp's 12 k-steps) ----
    const int rsel = lane & 15;
    const int ksel = (lane >> 4) << 4;
    const int koffB = upper * (KSP * 32);       // byte offset of k-step 12
    uint32_t a[KSP][4];
    {
        const uint32_t ab = sbase + (wlo * 16 + rsel) * ROWB + ksel + koffB;
        #pragma unroll
        for (int ks = 0; ks < KSP; ks++)
            ldsm_x4(a[ks][0], a[ks][1], a[ks][2], a[ks][3], ab + ks * 32);
    }
    __syncthreads();   // staging dead -> reuse as B double buffer

    // ---- prefetch B chunk 0 ----
    {
        const uint4* src = (const uint4*)(g_e2 + (size_t)(q * K_) * EPITCH);
        for (int u = tid; u < 64 * 49; u += 512) {
            int row = u / 49, c = u % 49;
            cp_async16(smem + SM_BUF0 + row * ROWB + c * 16, src + (size_t)row * 49 + c);
        }
        cp_async_commit();
    }

    float mb0 = -3.4e38f, mb1 = -3.4e38f;
    float cs0[NC], cs1[NC];
    int   ci0[NC], ci1[NC];
    int   cn0 = 0, cn1 = 0, ovf0 = 0, ovf1 = 0;

    const uint32_t bsel = rsel * ROWB + ksel + koffB;

    for (int ch = 0; ch < 16; ++ch) {
        cp_async_wait_all();
        __syncthreads();   // buffer ready; prev partials consumed

        if (ch < 15) {
            const uint4* src = (const uint4*)(g_e2 + (size_t)(q * K_ + (ch + 1) * 64) * EPITCH);
            char* dst = smem + (((ch + 1) & 1) ? SM_BUF1 : SM_BUF0);
            for (int u = tid; u < 64 * 49; u += 512) {
                int row = u / 49, c = u % 49;
                cp_async16(dst + row * ROWB + c * 16, src + (size_t)row * 49 + c);
            }
        }
        cp_async_commit();

        const uint32_t bb = sbase + ((ch & 1) ? SM_BUF1 : SM_BUF0) + bsel;

        float acc[8][4];
        #pragma unroll
        for (int i = 0; i < 8; i++)
            acc[i][0] = acc[i][1] = acc[i][2] = acc[i][3] = 0.0f;

        #pragma unroll
        for (int ks = 0; ks < KSP; ++ks) {
            #pragma unroll
            for (int n16 = 0; n16 < 4; n16++) {
                uint32_t b0, b1, b2, b3;
                ldsm_x4(b0, b1, b2, b3, bb + n16 * (16 * ROWB) + ks * 32);
                mma16816(acc[2 * n16],     a[ks], b0, b2);
                mma16816(acc[2 * n16 + 1], a[ks], b1, b3);
            }
        }

        // ---- upper warps publish partials ----
        if (upper) {
            float4* dst = part + (size_t)(wlo * 32 + lane) * 8;
            #pragma unroll
            for (int i = 0; i < 8; i++)
                dst[i] = make_float4(acc[i][0], acc[i][1], acc[i][2], acc[i][3]);
        }
        __syncthreads();

        // ---- lower warps combine + scan ----
        if (!upper) {
            const float4* srcp = part + (size_t)(wlo * 32 + lane) * 8;
            #pragma unroll
            for (int i = 0; i < 8; i++) {
                const float4 p = srcp[i];
                acc[i][0] += p.x; acc[i][1] += p.y;
                acc[i][2] += p.z; acc[i][3] += p.w;
            }
            #pragma unroll
            for (int n8 = 0; n8 < 8; n8++) {
                const int ncol = n8 * 8 + (lane & 3) * 2;
                #pragma unroll
                for (int e = 0; e < 2; e++) {
                    const int idx = ch * 64 + ncol + e;
                    const float cnv = gcn[idx];
                    {
                        const float s = 2.0f * acc[n8][e] - cnv;
                        CAND_UPD(s, idx, mb0, cs0, ci0, cn0, ovf0);
                    }
                    {
                        const float s = 2.0f * acc[n8][2 + e] - cnv;
                        CAND_UPD(s, idx, mb1, cs1, ci1, cn1, ovf1);
                    }
                }
            }
        }
    }
    cp_async_wait_all();

    // ---- per-point merge + exact rescore (lower warps only) ----
    if (!upper) {
        const int prow0 = wlo * 16 + (lane >> 2);
        const int prow1 = prow0 + 8;
        float gm0 = mb0, gm1 = mb1;
        #pragma unroll
        for (int d = 1; d < 4; d <<= 1) {
            gm0 = fmaxf(gm0, __shfl_xor_sync(0xffffffffu, gm0, d));
            gm1 = fmaxf(gm1, __shfl_xor_sync(0xffffffffu, gm1, d));
            ovf0 |= __shfl_xor_sync(0xffffffffu, ovf0, d);
            ovf1 |= __shfl_xor_sync(0xffffffffu, ovf1, d);
        }

        int n0 = blockStart + prow0; if (n0 >= N_) n0 = 0;
        int n1 = blockStart + prow1; if (n1 >= N_) n1 = 0;

        auto score_exact = [&](int nn, int idx) -> float {
            const float* rr = g_resid + (size_t)nn * D_;
            const float* e  = embed + ((size_t)q * K_ + idx) * D_;
            float aLo = 0.0f, aHi = 0.0f;
            #pragma unroll 4
            for (int d4 = 0; d4 < 32; d4++) {
                aLo = fmaf(rr[d4 * 4 + 0], __ldg(&e[d4 * 4 + 0]), aLo);
                aHi = fmaf(rr[d4 * 4 + 1], __ldg(&e[d4 * 4 + 1]), aHi);
                aLo = fmaf(rr[d4 * 4 + 2], __ldg(&e[d4 * 4 + 2]), aLo);
                aHi = fmaf(rr[d4 * 4 + 3], __ldg(&e[d4 * 4 + 3]), aHi);
            }
            return 2.0f * (aLo + aHi) - gcn[idx];
        };

        float bE0 = -3.4e38f, bE1 = -3.4e38f;
        int   bI0 = 0x7fffffff, bI1 = 0x7fffffff;
        for (int t = 0; t < cn0; t++) {
            if (cs0[t] < gm0 - WIN) continue;
            const float s = score_exact(n0, ci0[t]);
            if (s > bE0 || (s == bE0 && ci0[t] < bI0)) { bE0 = s; bI0 = ci0[t]; }
        }
        for (int t = 0; t < cn1; t++) {
            if (cs1[t] < gm1 - WIN) continue;
            const float s = score_exact(n1, ci1[t]);
            if (s > bE1 || (s == bE1 && ci1[t] < bI1)) { bE1 = s; bI1 = ci1[t]; }
        }
        #pragma unroll
        for (int d = 1; d < 4; d <<= 1) {
            const float oe0 = __shfl_xor_sync(0xffffffffu, bE0, d);
            const int   oi0 = __shfl_xor_sync(0xffffffffu, bI0, d);
            if (oe0 > bE0 || (oe0 == bE0 && oi0 < bI0)) { bE0 = oe0; bI0 = oi0; }
            const float oe1 = __shfl_xor_sync(0xffffffffu, bE1, d);
            const int   oi1 = __shfl_xor_sync(0xffffffffu, bI1, d);
            if (oe1 > bE1 || (oe1 == bE1 && oi1 < bI1)) { bE1 = oe1; bI1 = oi1; }
        }
        if ((lane & 3) == 0) {
            if (ovf0) {
                bE0 = -3.4e38f; bI0 = 0;
                for (int idx = 0; idx < K_; idx++) {
                    const float s = score_exact(n0, idx);
                    if (s > bE0) { bE0 = s; bI0 = idx; }
                }
            }
            if (ovf1) {
                bE1 = -3.4e38f; bI1 = 0;
                for (int idx = 0; idx < K_; idx++) {
                    const float s = score_exact(n1, idx);
                    if (s > bE1) { bE1 = s; bI1 = idx; }
                }
            }
            sidx[prow0] = (bI0 == 0x7fffffff) ? 0 : bI0;
            sidx[prow1] = (bI1 == 0x7fffffff) ? 0 : bI1;
        }
    }
    __syncthreads();

    // ---- write indices as float ----
    if (tid < 128) {
        int n = blockStart + tid;
        if (n < N_) out[(size_t)q * N_ + n] = (float)sidx[tid];
    }

    // ---- residual update: r - e[best] -> g_resid ----
    const float4* eq4 = (const float4*)(embed + (size_t)q * K_ * D_);
    float4* rg4 = (float4*)g_resid;
    #pragma unroll
    for (int i = 0; i < 8; i++) {
        int f = tid + 512 * i;
        int pp = f >> 5, d4 = f & 31;
        int n = blockStart + pp;
        if (n < N_) {
            float4 r = rg4[(size_t)n * 32 + d4];
            float4 e = eq4[(size_t)sidx[pp] * 32 + d4];
            float4 w;
            w.x = r.x - e.x; w.y = r.y - e.y; w.z = r.z - e.z; w.w = r.w - e.w;
            rg4[(size_t)n * 32 + d4] = w;
        }
    }
}

// ---------------------------------------------------------------------------
extern "C" void kernel_launch(void* const* d_in, const int* in_sizes, int n_in,
                              void* d_out, int out_size)
{
    const float* embeddings = (const float*)d_in[0];
    const float* embed      = (const float*)d_in[1];
    if (n_in >= 2 && in_sizes[0] == Q_ * K_ * D_ && in_sizes[1] == B_ * D_ * T_) {
        const float* t = embeddings; embeddings = embed; embed = t;
    }
    float* out = (float*)d_out;

    cudaFuncSetAttribute(rvq_mma_kernel,
                         cudaFuncAttributeMaxDynamicSharedMemorySize, SM_TOTAL);

    transpose_kernel<<<dim3(71, 4, 32), dim3(32, 8)>>>(embeddings);
    cnorm_kernel<<<4096, 256>>>(embed);
    prep_e2_kernel<<<Q_ * K_, 128>>>(embed);
    for (int q = 0; q < Q_; q++) {
        rvq_mma_kernel<<<NBLK, 512, SM_TOTAL>>>(embed, q, out);
    }
}

// round 15
// speedup vs baseline: 1.2767x; 1.2767x over previous
#include <cuda_runtime.h>
#include <cuda_bf16.h>
#include <cstdint>

#define B_ 32
#define D_ 128
#define T_ 2250
#define Q_ 32
#define K_ 1024
#define N_ (B_*T_)          // 72000
#define NBLK 563            // ceil(N/128)
#define WIN 0.02f
#define NC 4                // candidate slots per lane per point

#define EPITCH 392          // bf16 per padded row (784 B)
#define ROWB 784

__device__ __align__(16) float g_resid[(size_t)N_ * D_];
__device__ __align__(16) float g_cnorm[Q_ * K_];
__device__ __align__(16) __nv_bfloat16 g_e2[(size_t)Q_ * K_ * EPITCH];

// ---------------------------------------------------------------------------
__global__ void transpose_kernel(const float* __restrict__ in)
{
    __shared__ float tile[32][33];
    const int b  = blockIdx.z;
    const int t0 = blockIdx.x * 32;
    const int d0 = blockIdx.y * 32;
    const int tx = threadIdx.x;
    const int ty = threadIdx.y;

    #pragma unroll
    for (int k = 0; k < 4; k++) {
        int d = d0 + ty + k * 8;
        int t = t0 + tx;
        float v = 0.0f;
        if (t < T_) v = in[((size_t)b * D_ + d) * T_ + t];
        tile[ty + k * 8][tx] = v;
    }
    __syncthreads();
    #pragma unroll
    for (int k = 0; k < 4; k++) {
        int t = t0 + ty + k * 8;
        int d = d0 + tx;
        if (t < T_) g_resid[((size_t)b * T_ + t) * D_ + d] = tile[tx][ty + k * 8];
    }
}

// ---------------------------------------------------------------------------
__global__ void cnorm_kernel(const float* __restrict__ embed)
{
    const int wid  = threadIdx.x >> 5;
    const int lane = threadIdx.x & 31;
    const int code = blockIdx.x * 8 + wid;
    float s = 0.0f;
    #pragma unroll
    for (int j = 0; j < 4; j++) {
        float v = embed[(size_t)code * D_ + lane + 32 * j];
        s = fmaf(v, v, s);
    }
    #pragma unroll
    for (int d = 16; d; d >>= 1) s += __shfl_xor_sync(0xffffffffu, s, d);
    if (lane == 0) g_cnorm[code] = s;
}

// ---------------------------------------------------------------------------
__global__ void prep_e2_kernel(const float* __restrict__ embed)
{
    const int row = blockIdx.x;
    const int d   = threadIdx.x;
    float v = embed[(size_t)row * D_ + d];
    __nv_bfloat16 hi = __float2bfloat16(v);
    __nv_bfloat16 lo = __float2bfloat16(v - __bfloat162float(hi));
    g_e2[(size_t)row * EPITCH + d]       = hi;
    g_e2[(size_t)row * EPITCH + 128 + d] = lo;
    g_e2[(size_t)row * EPITCH + 256 + d] = hi;
    if (d < 8) g_e2[(size_t)row * EPITCH + 384 + d] = __float2bfloat16(0.0f);
}

// ---------------------------------------------------------------------------
__device__ __forceinline__ uint32_t smem_u32(const void* p) {
    uint32_t a;
    asm("{ .reg .u64 t; cvta.to.shared.u64 t, %1; cvt.u32.u64 %0, t; }"
        : "=r"(a) : "l"(p));
    return a;
}
__device__ __forceinline__ void ldsm_x4(uint32_t& r0, uint32_t& r1,
                                        uint32_t& r2, uint32_t& r3, uint32_t addr)
{
    asm volatile("ldmatrix.sync.aligned.m8n8.x4.shared.b16 {%0,%1,%2,%3}, [%4];"
                 : "=r"(r0), "=r"(r1), "=r"(r2), "=r"(r3) : "r"(addr));
}
__device__ __forceinline__ void mma16816(float* c, const uint32_t* a,
                                         uint32_t b0, uint32_t b1)
{
    asm volatile(
        "mma.sync.aligned.m16n8k16.row.col.f32.bf16.bf16.f32 "
        "{%0,%1,%2,%3}, {%4,%5,%6,%7}, {%8,%9}, {%0,%1,%2,%3};"
        : "+f"(c[0]), "+f"(c[1]), "+f"(c[2]), "+f"(c[3])
        : "r"(a[0]), "r"(a[1]), "r"(a[2]), "r"(a[3]), "r"(b0), "r"(b1));
}
__device__ __forceinline__ void cp_async16(void* smem_dst, const void* gmem_src)
{
    unsigned saddr = (unsigned)__cvta_generic_to_shared(smem_dst);
    asm volatile("cp.async.cg.shared.global [%0], [%1], 16;"
                 :: "r"(saddr), "l"(gmem_src) : "memory");
}
__device__ __forceinline__ void cp_async_commit()
{ asm volatile("cp.async.commit_group;" ::: "memory"); }
__device__ __forceinline__ void cp_async_wait_all()
{ asm volatile("cp.async.wait_group 0;" ::: "memory"); }

#define CAND_UPD(s, idx, mb, cs, ci, cn, ovf) do {                            \
    if ((s) > (mb)) (mb) = (s);                                               \
    if ((s) >= (mb) - WIN) {                                                  \
        if ((cn) < NC) { (cs)[(cn)] = (s); (ci)[(cn)] = (idx); (cn)++; }      \
        else {                                                                \
            int _w = 0;                                                       \
            _Pragma("unroll")                                                 \
            for (int _t = 0; _t < NC; _t++)                                   \
                if ((cs)[_t] >= (mb) - WIN) {                                 \
                    (cs)[_w] = (cs)[_t]; (ci)[_w] = (ci)[_t]; _w++; }         \
            if (_w < NC) { (cs)[_w] = (s); (ci)[_w] = (idx); (cn) = _w + 1; } \
            else (ovf) = 1;                                                   \
        }                                                                     \
    }                                                                         \
} while (0)

// ---------------------------------------------------------------------------
// HMMA RVQ layer = R12 structure + two-phase (screen-then-book) scan.
// 256 threads = 8 warps; warp w owns M-rows [w*16, w*16+16), all N=64.
// A' fragments register-resident (24 k16-steps). Per chunk the scan first
// computes each point's 16-score max via an fmax tree; only chunks whose max
// reaches the running window trigger candidate bookkeeping. Final selection
// (exact fp32 rescore, R7 f32x2 order, first-max) unchanged -> same indices.
// ---------------------------------------------------------------------------
#define SM_BUF0 0
#define SM_BUF1 50176
#define SM_CN   100352
#define SM_SIDX 104448
#define SM_TOTAL 104960

__global__ void __launch_bounds__(256, 1)
rvq_mma_kernel(const float* __restrict__ embed, int q, float* __restrict__ out)
{
    extern __shared__ char smem[];
    float* gcn  = (float*)(smem + SM_CN);
    int*   sidx = (int*)(smem + SM_SIDX);
    const uint32_t sbase = smem_u32(smem);

    const int tid  = threadIdx.x;
    const int wid  = tid >> 5;
    const int lane = tid & 31;
    const int blockStart = blockIdx.x * 128;

    // ---- cnorm -> smem ----
    for (int u = tid; u < K_; u += 256) gcn[u] = g_cnorm[q * K_ + u];

    // ---- build A' staging = [r_hi | r_hi | r_lo] (128 x 384 bf16) ----
    for (int u = tid; u < 128 * 48; u += 256) {
        int row = u / 48, g = u % 48;
        int sec = g >> 4;
        int dbase = (g & 15) * 8;
        int n = blockStart + row;
        if (n >= N_) n = 0;
        const float* rr = g_resid + (size_t)n * D_;
        union { __nv_bfloat16 h[8]; uint4 v; } pk;
        #pragma unroll
        for (int j = 0; j < 8; j++) {
            float v = rr[dbase + j];
            __nv_bfloat16 hi = __float2bfloat16(v);
            pk.h[j] = (sec < 2) ? hi : __float2bfloat16(v - __bfloat162float(hi));
        }
        *(uint4*)(smem + row * ROWB + g * 16) = pk.v;
    }
    __syncthreads();

    // ---- A fragments -> registers ----
    const int rsel = lane & 15;
    const int ksel = (lane >> 4) << 4;
    uint32_t a[24][4];
    {
        const uint32_t ab = sbase + (wid * 16 + rsel) * ROWB + ksel;
        #pragma unroll
        for (int ks = 0; ks < 24; ks++)
            ldsm_x4(a[ks][0], a[ks][1], a[ks][2], a[ks][3], ab + ks * 32);
    }
    __syncthreads();   // staging dead -> reuse as B double buffer

    // ---- prefetch B chunk 0 ----
    {
        const uint4* src = (const uint4*)(g_e2 + (size_t)(q * K_) * EPITCH);
        for (int u = tid; u < 64 * 49; u += 256) {
            int row = u / 49, c = u % 49;
            cp_async16(smem + SM_BUF0 + row * ROWB + c * 16, src + (size_t)row * 49 + c);
        }
        cp_async_commit();
    }

    float mb0 = -3.4e38f, mb1 = -3.4e38f;
    float cs0[NC], cs1[NC];
    int   ci0[NC], ci1[NC];
    int   cn0 = 0, cn1 = 0, ovf0 = 0, ovf1 = 0;

    const uint32_t bsel = rsel * ROWB + ksel;

    for (int ch = 0; ch < 16; ++ch) {
        cp_async_wait_all();
        __syncthreads();   // buffer ch&1 ready; prior readers done with it

        if (ch < 15) {
            const uint4* src = (const uint4*)(g_e2 + (size_t)(q * K_ + (ch + 1) * 64) * EPITCH);
            char* dst = smem + (((ch + 1) & 1) ? SM_BUF1 : SM_BUF0);
            for (int u = tid; u < 64 * 49; u += 256) {
                int row = u / 49, c = u % 49;
                cp_async16(dst + row * ROWB + c * 16, src + (size_t)row * 49 + c);
            }
        }
        cp_async_commit();

        const uint32_t bb = sbase + ((ch & 1) ? SM_BUF1 : SM_BUF0) + bsel;

        float acc[8][4];
        #pragma unroll
        for (int i = 0; i < 8; i++)
            acc[i][0] = acc[i][1] = acc[i][2] = acc[i][3] = 0.0f;

        #pragma unroll
        for (int ks = 0; ks < 24; ++ks) {
            #pragma unroll
            for (int n16 = 0; n16 < 4; n16++) {
                uint32_t b0, b1, b2, b3;
                ldsm_x4(b0, b1, b2, b3, bb + n16 * (16 * ROWB) + ks * 32);
                mma16816(acc[2 * n16],     a[ks], b0, b2);
                mma16816(acc[2 * n16 + 1], a[ks], b1, b3);
            }
        }

        // ---- two-phase scan ----
        // cn cache: same 16 columns serve both points of this lane
        float cnv[16];
        #pragma unroll
        for (int n8 = 0; n8 < 8; n8++) {
            const int ncol = n8 * 8 + (lane & 3) * 2;
            cnv[2 * n8]     = gcn[ch * 64 + ncol];
            cnv[2 * n8 + 1] = gcn[ch * 64 + ncol + 1];
        }
        // phase 1: score maxima via fmax tree (no branches)
        float smax0 = -3.4e38f, smax1 = -3.4e38f;
        #pragma unroll
        for (int n8 = 0; n8 < 8; n8++) {
            #pragma unroll
            for (int e = 0; e < 2; e++) {
                smax0 = fmaxf(smax0, fmaf(2.0f, acc[n8][e],     -cnv[2 * n8 + e]));
                smax1 = fmaxf(smax1, fmaf(2.0f, acc[n8][2 + e], -cnv[2 * n8 + e]));
            }
        }
        // phase 2: bookkeeping only when the chunk can reach the window
        if (smax0 >= mb0 - WIN) {
            #pragma unroll
            for (int n8 = 0; n8 < 8; n8++) {
                const int ncol = n8 * 8 + (lane & 3) * 2;
                #pragma unroll
                for (int e = 0; e < 2; e++) {
                    const int idx = ch * 64 + ncol + e;
                    const float s = fmaf(2.0f, acc[n8][e], -cnv[2 * n8 + e]);
                    CAND_UPD(s, idx, mb0, cs0, ci0, cn0, ovf0);
                }
            }
        }
        if (smax1 >= mb1 - WIN) {
            #pragma unroll
            for (int n8 = 0; n8 < 8; n8++) {
                const int ncol = n8 * 8 + (lane & 3) * 2;
                #pragma unroll
                for (int e = 0; e < 2; e++) {
                    const int idx = ch * 64 + ncol + e;
                    const float s = fmaf(2.0f, acc[n8][2 + e], -cnv[2 * n8 + e]);
                    CAND_UPD(s, idx, mb1, cs1, ci1, cn1, ovf1);
                }
            }
        }
    }
    cp_async_wait_all();

    // ---- per-point merge + exact rescore ----
    const int prow0 = wid * 16 + (lane >> 2);
    const int prow1 = prow0 + 8;
    float gm0 = mb0, gm1 = mb1;
    #pragma unroll
    for (int d = 1; d < 4; d <<= 1) {
        gm0 = fmaxf(gm0, __shfl_xor_sync(0xffffffffu, gm0, d));
        gm1 = fmaxf(gm1, __shfl_xor_sync(0xffffffffu, gm1, d));
        ovf0 |= __shfl_xor_sync(0xffffffffu, ovf0, d);
        ovf1 |= __shfl_xor_sync(0xffffffffu, ovf1, d);
    }

    int n0 = blockStart + prow0; if (n0 >= N_) n0 = 0;
    int n1 = blockStart + prow1; if (n1 >= N_) n1 = 0;

    auto score_exact = [&](int nn, int idx) -> float {
        const float* rr = g_resid + (size_t)nn * D_;
        const float* e  = embed + ((size_t)q * K_ + idx) * D_;
        float aLo = 0.0f, aHi = 0.0f;
        #pragma unroll 4
        for (int d4 = 0; d4 < 32; d4++) {
            aLo = fmaf(rr[d4 * 4 + 0], __ldg(&e[d4 * 4 + 0]), aLo);
            aHi = fmaf(rr[d4 * 4 + 1], __ldg(&e[d4 * 4 + 1]), aHi);
            aLo = fmaf(rr[d4 * 4 + 2], __ldg(&e[d4 * 4 + 2]), aLo);
            aHi = fmaf(rr[d4 * 4 + 3], __ldg(&e[d4 * 4 + 3]), aHi);
        }
        return 2.0f * (aLo + aHi) - gcn[idx];
    };

    float bE0 = -3.4e38f, bE1 = -3.4e38f;
    int   bI0 = 0x7fffffff, bI1 = 0x7fffffff;
    for (int t = 0; t < cn0; t++) {
        if (cs0[t] < gm0 - WIN) continue;
        const float s = score_exact(n0, ci0[t]);
        if (s > bE0 || (s == bE0 && ci0[t] < bI0)) { bE0 = s; bI0 = ci0[t]; }
    }
    for (int t = 0; t < cn1; t++) {
        if (cs1[t] < gm1 - WIN) continue;
        const float s = score_exact(n1, ci1[t]);
        if (s > bE1 || (s == bE1 && ci1[t] < bI1)) { bE1 = s; bI1 = ci1[t]; }
    }
    #pragma unroll
    for (int d = 1; d < 4; d <<= 1) {
        const float oe0 = __shfl_xor_sync(0xffffffffu, bE0, d);
        const int   oi0 = __shfl_xor_sync(0xffffffffu, bI0, d);
        if (oe0 > bE0 || (oe0 == bE0 && oi0 < bI0)) { bE0 = oe0; bI0 = oi0; }
        const float oe1 = __shfl_xor_sync(0xffffffffu, bE1, d);
        const int   oi1 = __shfl_xor_sync(0xffffffffu, bI1, d);
        if (oe1 > bE1 || (oe1 == bE1 && oi1 < bI1)) { bE1 = oe1; bI1 = oi1; }
    }
    if ((lane & 3) == 0) {
        if (ovf0) {
            bE0 = -3.4e38f; bI0 = 0;
            for (int idx = 0; idx < K_; idx++) {
                const float s = score_exact(n0, idx);
                if (s > bE0) { bE0 = s; bI0 = idx; }
            }
        }
        if (ovf1) {
            bE1 = -3.4e38f; bI1 = 0;
            for (int idx = 0; idx < K_; idx++) {
                const float s = score_exact(n1, idx);
                if (s > bE1) { bE1 = s; bI1 = idx; }
            }
        }
        sidx[prow0] = (bI0 == 0x7fffffff) ? 0 : bI0;
        sidx[prow1] = (bI1 == 0x7fffffff) ? 0 : bI1;
    }
    __syncthreads();

    // ---- write indices as float ----
    if (tid < 128) {
        int n = blockStart + tid;
        if (n < N_) out[(size_t)q * N_ + n] = (float)sidx[tid];
    }

    // ---- residual update: r - e[best] -> g_resid ----
    const float4* eq4 = (const float4*)(embed + (size_t)q * K_ * D_);
    float4* rg4 = (float4*)g_resid;
    #pragma unroll
    for (int i = 0; i < 16; i++) {
        int f = tid + 256 * i;
        int pp = f >> 5, d4 = f & 31;
        int n = blockStart + pp;
        if (n < N_) {
            float4 r = rg4[(size_t)n * 32 + d4];
            float4 e = eq4[(size_t)sidx[pp] * 32 + d4];
            float4 w;
            w.x = r.x - e.x; w.y = r.y - e.y; w.z = r.z - e.z; w.w = r.w - e.w;
            rg4[(size_t)n * 32 + d4] = w;
        }
    }
}

// ---------------------------------------------------------------------------
extern "C" void kernel_launch(void* const* d_in, const int* in_sizes, int n_in,
                              void* d_out, int out_size)
{
    const float* embeddings = (const float*)d_in[0];
    const float* embed      = (const float*)d_in[1];
    if (n_in >= 2 && in_sizes[0] == Q_ * K_ * D_ && in_sizes[1] == B_ * D_ * T_) {
        const float* t = embeddings; embeddings = embed; embed = t;
    }
    float* out = (float*)d_out;

    cudaFuncSetAttribute(rvq_mma_kernel,
                         cudaFuncAttributeMaxDynamicSharedMemorySize, SM_TOTAL);

    transpose_kernel<<<dim3(71, 4, 32), dim3(32, 8)>>>(embeddings);
    cnorm_kernel<<<4096, 256>>>(embed);
    prep_e2_kernel<<<Q_ * K_, 128>>>(embed);
    for (int q = 0; q < Q_; q++) {
        rvq_mma_kernel<<<NBLK, 256, SM_TOTAL>>>(embed, q, out);
    }
}